// round 9
// baseline (speedup 1.0000x reference)
#include <cuda_runtime.h>
#include <cuda_fp16.h>
#include <cstdint>

// ---------------------------------------------------------------------------
// 3-layer GAT, N=50000 nodes, E=800000 edges.
// R9: subwarp aggregation (16-lane subwarp = 1 fp16 row; 2 nodes/warp for
//     O=128, 4 for O=64), memset-based CSR zero, earlier join event.
//     GEMM = mma.sync m16n8k8 tf32 with fused scores + fused embedding.
// ---------------------------------------------------------------------------

#define NMAX 50000
#define EMAX 800000

__device__ float g_hA[NMAX * 128];
__device__ float g_hB[NMAX * 128];
__device__ float g_fh[NMAX * 128];   // used as __half[NMAX*128]
__device__ float g_el[NMAX * 2];
__device__ float g_er[NMAX * 2];
__device__ float g_Wc[128 * 128];
__device__ int   g_row[NMAX + 1];
__device__ int   g_cur[NMAX];
__device__ int   g_col[EMAX];
__device__ int   g_bsum[64];

__device__ __forceinline__ float lrelu(float v) { return v > 0.f ? v : 0.2f * v; }

__device__ __forceinline__ uint32_t f2tf32(float f) {
    uint32_t r;
    asm("cvt.rna.tf32.f32 %0, %1;" : "=r"(r) : "f"(f));
    return r;
}

__device__ __forceinline__ void mma_tf32(float c[4], const uint32_t a[4],
                                         const uint32_t b[2]) {
    asm volatile(
        "mma.sync.aligned.m16n8k8.row.col.f32.tf32.tf32.f32 "
        "{%0,%1,%2,%3}, {%4,%5,%6,%7}, {%8,%9}, {%0,%1,%2,%3};"
        : "+f"(c[0]), "+f"(c[1]), "+f"(c[2]), "+f"(c[3])
        : "r"(a[0]), "r"(a[1]), "r"(a[2]), "r"(a[3]), "r"(b[0]), "r"(b[1]));
}

namespace {
struct ForkRes {
    cudaStream_t s1;
    cudaEvent_t e0, e1;
    ForkRes() {
        cudaStreamCreateWithFlags(&s1, cudaStreamNonBlocking);
        cudaEventCreateWithFlags(&e0, cudaEventDisableTiming);
        cudaEventCreateWithFlags(&e1, cudaEventDisableTiming);
    }
};
ForkRes g_fork;
}

// ---------------------------------------------------------------------------
// CSR build
// ---------------------------------------------------------------------------
__global__ void k_count(const int* __restrict__ dst, int* __restrict__ cnt, int E) {
    int e = blockIdx.x * blockDim.x + threadIdx.x;
    if (e < E) atomicAdd(&cnt[dst[e]], 1);
}
__global__ void k_bsum(const int* __restrict__ cnt, int* __restrict__ bsum, int N) {
    __shared__ int ws[32];
    int i = blockIdx.x * 1024 + threadIdx.x;
    int lane = threadIdx.x & 31, wid = threadIdx.x >> 5;
    int v = (i < N) ? cnt[i] : 0;
#pragma unroll
    for (int o = 16; o > 0; o >>= 1) v += __shfl_xor_sync(0xffffffffu, v, o);
    if (lane == 0) ws[wid] = v;
    __syncthreads();
    if (wid == 0) {
        int x = ws[lane];
#pragma unroll
        for (int o = 16; o > 0; o >>= 1) x += __shfl_xor_sync(0xffffffffu, x, o);
        if (lane == 0) bsum[blockIdx.x] = x;
    }
}
__global__ void k_bscan(int* __restrict__ bsum, int nb) {
    __shared__ int sh[64];
    int tid = threadIdx.x;
    int v = (tid < nb) ? bsum[tid] : 0;
    sh[tid] = v;
    __syncthreads();
#pragma unroll
    for (int o = 1; o < 64; o <<= 1) {
        int t = (tid >= o) ? sh[tid - o] : 0;
        __syncthreads();
        sh[tid] += t;
        __syncthreads();
    }
    if (tid < nb) bsum[tid] = sh[tid] - v;
}
__global__ void k_scan2(const int* __restrict__ cnt, const int* __restrict__ bsum,
                        int* __restrict__ row, int* __restrict__ cur, int N, int E) {
    __shared__ int ws[32];
    int i = blockIdx.x * 1024 + threadIdx.x;
    int lane = threadIdx.x & 31, wid = threadIdx.x >> 5;
    int v = (i < N) ? cnt[i] : 0;
    int x = v;
#pragma unroll
    for (int o = 1; o < 32; o <<= 1) {
        int t = __shfl_up_sync(0xffffffffu, x, o);
        if (lane >= o) x += t;
    }
    if (lane == 31) ws[wid] = x;
    __syncthreads();
    if (wid == 0) {
        int y = ws[lane];
#pragma unroll
        for (int o = 1; o < 32; o <<= 1) {
            int t = __shfl_up_sync(0xffffffffu, y, o);
            if (lane >= o) y += t;
        }
        ws[lane] = y;
    }
    __syncthreads();
    int excl = bsum[blockIdx.x] + (wid ? ws[wid - 1] : 0) + x - v;
    if (i < N) { row[i] = excl; cur[i] = excl; }
    if (i == 0) row[N] = E;
}
__global__ void k_scatter(const int* __restrict__ src, const int* __restrict__ dst,
                          int* __restrict__ cur, int* __restrict__ col, int E) {
    int e = blockIdx.x * blockDim.x + threadIdx.x;
    if (e >= E) return;
    int slot = atomicAdd(&cur[dst[e]], 1);
    col[slot] = src[e];
}
__global__ void k_wcat(const float* __restrict__ W2, const float* __restrict__ resW2,
                       float* __restrict__ Wc) {
    int i = blockIdx.x * blockDim.x + threadIdx.x;
    if (i >= 128 * 128) return;
    int k = i >> 7, j = i & 127;
    Wc[i] = (j < 64) ? W2[k * 64 + j] : resW2[k * 64 + (j - 64)];
}

// ---------------------------------------------------------------------------
// TF32 mma.sync GEMM + fused scores (unchanged from R8).
// ---------------------------------------------------------------------------
template <int K, int HS, bool SPLIT, bool EMB>
__global__ void __launch_bounds__(256)
k_mgemm(const float* __restrict__ A, const int* __restrict__ feats,
        const float* __restrict__ fv, const float* __restrict__ emb,
        const float* __restrict__ W,
        void* __restrict__ outh, float* __restrict__ out2,
        const float* __restrict__ al, const float* __restrict__ ar,
        float* __restrict__ el, float* __restrict__ er, int N) {
    extern __shared__ char smraw[];
    float*    stage = (float*)smraw;
    uint32_t* sW    = (uint32_t*)(smraw + 64 * 132 * 4);
    uint32_t* sA    = (uint32_t*)(smraw + 64 * 132 * 4 + K * 132 * 4);
    constexpr int SAS = K + 4;

    const int tid = threadIdx.x;
    const int wid = tid >> 5, lane = tid & 31;
    const int g = lane >> 2, t = lane & 3;
    const int row0 = blockIdx.x * 64;
    const int wRow = (wid >> 2) * 32, wCol = (wid & 3) * 32;

    for (int i = tid; i < K * 32; i += 256) {
        int k = i >> 5, c4 = i & 31;
        float4 v = *(const float4*)&W[k * 128 + c4 * 4];
        uint4 u;
        u.x = f2tf32(v.x); u.y = f2tf32(v.y); u.z = f2tf32(v.z); u.w = f2tf32(v.w);
        *(uint4*)&sW[k * 132 + c4 * 4] = u;
    }
    constexpr int C4 = K / 4;
    for (int i = tid; i < 64 * C4; i += 256) {
        int r = i / C4, c4 = i % C4, rr = row0 + r;
        float4 v = make_float4(0.f, 0.f, 0.f, 0.f);
        if (rr < N) {
            if (EMB) {
                float s = fv[rr];
                v = *(const float4*)&emb[(long long)feats[rr] * 64 + c4 * 4];
                v.x *= s; v.y *= s; v.z *= s; v.w *= s;
            } else {
                v = *(const float4*)&A[(size_t)rr * K + c4 * 4];
            }
        }
        uint4 u;
        u.x = f2tf32(v.x); u.y = f2tf32(v.y); u.z = f2tf32(v.z); u.w = f2tf32(v.w);
        *(uint4*)&sA[r * SAS + c4 * 4] = u;
    }
    __syncthreads();

    float c[2][4][4];
#pragma unroll
    for (int mf = 0; mf < 2; mf++)
#pragma unroll
        for (int nf = 0; nf < 4; nf++)
#pragma unroll
            for (int i = 0; i < 4; i++) c[mf][nf][i] = 0.f;

#pragma unroll
    for (int ks = 0; ks < K / 8; ks++) {
        const int k0 = ks * 8;
        uint32_t a[2][4];
#pragma unroll
        for (int mf = 0; mf < 2; mf++) {
            int rb = wRow + mf * 16;
            a[mf][0] = sA[(rb + g)     * SAS + k0 + t];
            a[mf][1] = sA[(rb + g + 8) * SAS + k0 + t];
            a[mf][2] = sA[(rb + g)     * SAS + k0 + t + 4];
            a[mf][3] = sA[(rb + g + 8) * SAS + k0 + t + 4];
        }
        uint32_t b[4][2];
#pragma unroll
        for (int nf = 0; nf < 4; nf++) {
            int cc = wCol + nf * 8 + g;
            b[nf][0] = sW[(k0 + t)     * 132 + cc];
            b[nf][1] = sW[(k0 + t + 4) * 132 + cc];
        }
#pragma unroll
        for (int mf = 0; mf < 2; mf++)
#pragma unroll
            for (int nf = 0; nf < 4; nf++)
                mma_tf32(c[mf][nf], a[mf], b[nf]);
    }
    __syncthreads();

#pragma unroll
    for (int mf = 0; mf < 2; mf++) {
#pragma unroll
        for (int nf = 0; nf < 4; nf++) {
            int ra = wRow + mf * 16 + g;
            int cc = wCol + nf * 8 + t * 2;
            *(float2*)&stage[ra * 132 + cc]       = make_float2(c[mf][nf][0], c[mf][nf][1]);
            *(float2*)&stage[(ra + 8) * 132 + cc] = make_float2(c[mf][nf][2], c[mf][nf][3]);
        }
    }
    __syncthreads();

    float4 a4 = make_float4(0.f, 0.f, 0.f, 0.f);
    float4 r4 = make_float4(0.f, 0.f, 0.f, 0.f);
    if (lane * 4 < HS * 64) {
        a4 = *(const float4*)&al[lane * 4];
        r4 = *(const float4*)&ar[lane * 4];
    }
    __half* fhh = (__half*)outh;
#pragma unroll
    for (int q = 0; q < 8; q++) {
        int r = wid * 8 + q;
        int rr = row0 + r;
        float4 f = *(const float4*)&stage[r * 132 + lane * 4];
        float sl = f.x * a4.x + f.y * a4.y + f.z * a4.z + f.w * a4.w;
        float sr = f.x * r4.x + f.y * r4.y + f.z * r4.z + f.w * r4.w;
#pragma unroll
        for (int off = 8; off > 0; off >>= 1) {
            sl += __shfl_xor_sync(0xffffffffu, sl, off);
            sr += __shfl_xor_sync(0xffffffffu, sr, off);
        }
        int h = lane >> 4;
        if ((lane & 15) == 0 && h < HS && rr < N) {
            el[rr * HS + h] = sl;
            er[rr * HS + h] = sr;
        }
        if (rr < N) {
            __half2 ha = __float22half2_rn(make_float2(f.x, f.y));
            __half2 hb = __float22half2_rn(make_float2(f.z, f.w));
            uint2 u;
            u.x = *(uint32_t*)&ha; u.y = *(uint32_t*)&hb;
            if (SPLIT) {
                if (lane < 16) *(uint2*)(fhh + (size_t)rr * 64 + lane * 4) = u;
                else           *(float4*)&out2[(size_t)rr * 64 + lane * 4 - 64] = f;
            } else {
                *(uint2*)(fhh + (size_t)rr * 128 + lane * 4) = u;
            }
        }
    }
}

// ---------------------------------------------------------------------------
// Subwarp fp16 aggregation. SW = O/8 lanes per subwarp = exactly one fh row
// (uint4/lane). Each subwarp owns one dst node; 32/SW nodes per warp.
// Edge phase: SW lanes load SW edges' col/p; gather phase: subwarp-broadcast
// (2-deep unroll for MLP) and full-row loads.
// ---------------------------------------------------------------------------
template <int O, int H, bool ELU>
__global__ void __launch_bounds__(256)
k_aggr(const int* __restrict__ row, const int* __restrict__ col,
       const float* __restrict__ el, const float* __restrict__ er,
       const void* __restrict__ fhv, const float* __restrict__ bias,
       const float* __restrict__ res, float* __restrict__ out, int N) {
    constexpr int SW = O / 8;      // 16 (O=128) or 8 (O=64)
    constexpr int NP = 32 / SW;    // nodes per warp
    const int lane = threadIdx.x & 31;
    const int subw = lane / SW, sub = lane % SW;
    const int warp = (int)((blockIdx.x * blockDim.x + threadIdx.x) >> 5);
    const int w = warp * NP + subw;
    if (w >= N) return;
    const unsigned mask = ((SW == 32) ? 0xffffffffu : ((1u << SW) - 1u)) << (subw * SW);
    const int c0 = sub * 8;
    const bool topHead = (H == 2) && (c0 >= 64);
    const __half* fhh = (const __half*)fhv;

    const float er0 = er[w * H + 0];
    const float er1 = (H == 2) ? er[w * H + 1] : 0.f;
    const int e0 = row[w], e1 = row[w + 1];

    float den0 = 0.f;
    float acc[2][8];
#pragma unroll
    for (int b = 0; b < 2; b++)
#pragma unroll
        for (int i = 0; i < 8; i++) acc[b][i] = 0.f;

    for (int base = e0; base < e1; base += SW) {
        int idx = base + sub;
        bool valid = idx < e1;
        int s_l = valid ? col[idx] : 0;
        float p_l = 0.f, pme_l = 0.f;   // p for my head; also track head-0 for den
        if (valid) {
            if (H == 2) {
                float2 ev = *(const float2*)&el[s_l * 2];
                float pa = __expf(lrelu(ev.x + er0));
                float pb = __expf(lrelu(ev.y + er1));
                pme_l = topHead ? pb : pa;
                // den: every lane accumulates BOTH? No: head-specific den is the
                // same for all lanes of that head; accumulate per-lane my-head p.
                p_l = pme_l;
            } else {
                p_l = __expf(lrelu(el[s_l] + er0));
                pme_l = p_l;
            }
            den0 += p_l;
        }
        int n = min(SW, e1 - base);
        for (int j = 0; j < n; j += 2) {
#pragma unroll
            for (int b = 0; b < 2; b++) {
                int sl2 = j + b;               // < SW (see analysis: j even, b<=1)
                int   s = __shfl_sync(mask, s_l,   sl2, SW);
                float p = __shfl_sync(mask, pme_l, sl2, SW);
                // lanes' pme differs per head but broadcast source lane's pme is
                // for the SOURCE lane's head — wrong. Need p for MY head from
                // source edge: broadcast both head p's instead.
                (void)p;
                uint4 u;
                float pa, pb, pm;
                if (H == 2) {
                    // recompute: broadcast s, load el for my head? cheaper:
                    // broadcast both heads' p.
                    pa = __shfl_sync(mask, p_l, sl2, SW);   // placeholder (fixed below)
                    (void)pa; (void)pb;
                }
                // NOTE: see corrected path below (pH0/pH1 broadcast).
                pm = 0.f;
                (void)pm; (void)u; (void)s;
            }
        }
        // The loop above is replaced by the corrected one below.
        break;
    }

    // ---- corrected main loop (broadcast both heads' p) ----
    den0 = 0.f;
#pragma unroll
    for (int b = 0; b < 2; b++)
#pragma unroll
        for (int i = 0; i < 8; i++) acc[b][i] = 0.f;

    for (int base = e0; base < e1; base += SW) {
        int idx = base + sub;
        bool valid = idx < e1;
        int s_l = valid ? col[idx] : 0;
        float p0_l = 0.f, p1_l = 0.f;
        if (valid) {
            if (H == 2) {
                float2 ev = *(const float2*)&el[s_l * 2];
                p0_l = __expf(lrelu(ev.x + er0));
                p1_l = __expf(lrelu(ev.y + er1));
            } else {
                p0_l = __expf(lrelu(el[s_l] + er0));
            }
            den0 += topHead ? p1_l : p0_l;
        }
        int n = min(SW, e1 - base);
        for (int j = 0; j < n; j += 2) {
#pragma unroll
            for (int b = 0; b < 2; b++) {
                int sl2 = j + b;
                int   s  = __shfl_sync(mask, s_l,  sl2, SW);
                float pa = __shfl_sync(mask, p0_l, sl2, SW);
                float p;
                if (H == 2) {
                    float pb = __shfl_sync(mask, p1_l, sl2, SW);
                    p = topHead ? pb : pa;
                } else p = pa;
                uint4 u = *(const uint4*)(fhh + (size_t)s * O + c0);
                float2 f0 = __half22float2(*(__half2*)&u.x);
                float2 f1 = __half22float2(*(__half2*)&u.y);
                float2 f2 = __half22float2(*(__half2*)&u.z);
                float2 f3 = __half22float2(*(__half2*)&u.w);
                acc[b][0] += p * f0.x; acc[b][1] += p * f0.y;
                acc[b][2] += p * f1.x; acc[b][3] += p * f1.y;
                acc[b][4] += p * f2.x; acc[b][5] += p * f2.y;
                acc[b][6] += p * f3.x; acc[b][7] += p * f3.y;
            }
        }
    }

    // den: sum over lanes of MY head within subwarp. For H=2, lanes 0..7 hold
    // head0 contributions, 8..15 head1 — but every valid lane accumulated its
    // own edge's p for ITS head; edges are spread over all SW lanes, so den
    // for my head needs p of ALL edges for my head: accumulate via both-head
    // broadcast instead: redo with full reduce of p0/p1 separately.
    // Simpler correct scheme: each lane re-accumulates den from broadcasts.
    // (den0 above is wrong; recompute cheaply below.)
    float den = 0.f;
    for (int base = e0; base < e1; base += SW) {
        int idx = base + sub;
        bool valid = idx < e1;
        float pm = 0.f;
        if (valid) {
            int s_l = col[idx];
            if (H == 2) {
                float2 ev = *(const float2*)&el[s_l * 2];
                pm = topHead ? __expf(lrelu(ev.y + er1)) : __expf(lrelu(ev.x + er0));
            } else {
                pm = __expf(lrelu(el[s_l] + er0));
            }
        }
        den += pm;
    }
#pragma unroll
    for (int o = SW / 2; o > 0; o >>= 1)
        den += __shfl_xor_sync(mask, den, o, SW);
    // lanes of the same head within the subwarp now all hold... NOTE: this
    // sums over ALL subwarp lanes (both heads' lanes), but each lane
    // contributed p for ITS OWN head -> mixed. Guard: for H=2 the per-lane pm
    // above used the lane's head, so the reduction mixes heads. Fix by
    // accumulating both dens and selecting:
    float d0 = 0.f, d1 = 0.f;
    for (int base = e0; base < e1; base += SW) {
        int idx = base + sub;
        if (idx < e1) {
            int s_l = col[idx];
            if (H == 2) {
                float2 ev = *(const float2*)&el[s_l * 2];
                d0 += __expf(lrelu(ev.x + er0));
                d1 += __expf(lrelu(ev.y + er1));
            } else {
                d0 += __expf(lrelu(el[s_l] + er0));
            }
        }
    }
#pragma unroll
    for (int o = SW / 2; o > 0; o >>= 1) {
        d0 += __shfl_xor_sync(mask, d0, o, SW);
        if (H == 2) d1 += __shfl_xor_sync(mask, d1, o, SW);
    }
    den = (H == 2 && topHead) ? d1 : d0;

    float inv = 1.f / fmaxf(den, 1e-9f);
    float4 bva = *(const float4*)&bias[c0];
    float4 bvb = *(const float4*)&bias[c0 + 4];
    float4 ra = make_float4(0.f, 0.f, 0.f, 0.f), rb = ra;
    if (res) {
        ra = *(const float4*)&res[(size_t)w * O + c0];
        rb = *(const float4*)&res[(size_t)w * O + c0 + 4];
    }
    float o8[8];
    float s0 = acc[0][0] + acc[1][0], s1 = acc[0][1] + acc[1][1];
    float s2 = acc[0][2] + acc[1][2], s3 = acc[0][3] + acc[1][3];
    float s4 = acc[0][4] + acc[1][4], s5 = acc[0][5] + acc[1][5];
    float s6 = acc[0][6] + acc[1][6], s7 = acc[0][7] + acc[1][7];
    o8[0] = s0 * inv + bva.x + ra.x;
    o8[1] = s1 * inv + bva.y + ra.y;
    o8[2] = s2 * inv + bva.z + ra.z;
    o8[3] = s3 * inv + bva.w + ra.w;
    o8[4] = s4 * inv + bvb.x + rb.x;
    o8[5] = s5 * inv + bvb.y + rb.y;
    o8[6] = s6 * inv + bvb.z + rb.z;
    o8[7] = s7 * inv + bvb.w + rb.w;
    if (ELU) {
#pragma unroll
        for (int i = 0; i < 8; i++)
            o8[i] = o8[i] > 0.f ? o8[i] : (__expf(o8[i]) - 1.f);
    }
    *(float4*)&out[(size_t)w * O + c0]     = make_float4(o8[0], o8[1], o8[2], o8[3]);
    *(float4*)&out[(size_t)w * O + c0 + 4] = make_float4(o8[4], o8[5], o8[6], o8[7]);
}

// ---------------------------------------------------------------------------
extern "C" void kernel_launch(void* const* d_in, const int* in_sizes, int n_in,
                              void* d_out, int out_size) {
    const int*   feats = (const int*)  d_in[0];
    const float* fv    = (const float*)d_in[1];
    const int*   src   = (const int*)  d_in[2];
    const int*   dst   = (const int*)  d_in[3];
    const float* emb   = (const float*)d_in[4];
    const float* W0    = (const float*)d_in[5];
    const float* al0   = (const float*)d_in[6];
    const float* ar0   = (const float*)d_in[7];
    const float* b0    = (const float*)d_in[8];
    const float* W1    = (const float*)d_in[9];
    const float* al1   = (const float*)d_in[10];
    const float* ar1   = (const float*)d_in[11];
    const float* b1    = (const float*)d_in[12];
    const float* W2    = (const float*)d_in[13];
    const float* al2   = (const float*)d_in[14];
    const float* ar2   = (const float*)d_in[15];
    const float* b2    = (const float*)d_in[16];
    const float* resW2 = (const float*)d_in[17];
    float* out = (float*)d_out;

    const int N = in_sizes[0] / 8;
    const int E = in_sizes[2];

    float *hA, *hB, *fh, *el, *er, *Wc;
    int *row, *cur, *col, *bsum;
    cudaGetSymbolAddress((void**)&hA,   g_hA);
    cudaGetSymbolAddress((void**)&hB,   g_hB);
    cudaGetSymbolAddress((void**)&fh,   g_fh);
    cudaGetSymbolAddress((void**)&el,   g_el);
    cudaGetSymbolAddress((void**)&er,   g_er);
    cudaGetSymbolAddress((void**)&Wc,   g_Wc);
    cudaGetSymbolAddress((void**)&row,  g_row);
    cudaGetSymbolAddress((void**)&cur,  g_cur);
    cudaGetSymbolAddress((void**)&col,  g_col);
    cudaGetSymbolAddress((void**)&bsum, g_bsum);

    const int TB = 256;
    const int gB = (N + 63) / 64;
    const int nb = (N + 1023) / 1024;
    // subwarp aggr block counts: warps = ceil(N/NP); blocks = ceil(warps/8)
    const int aggrB128 = ((N + 1) / 2 + 7) / 8;   // NP=2
    const int aggrB64  = ((N + 3) / 4 + 7) / 8;   // NP=4

    const int SM64  = 64 * 132 * 4 + 64 * 132 * 4  + 64 * (64 + 4)  * 4;
    const int SM128 = 64 * 132 * 4 + 128 * 132 * 4 + 64 * (128 + 4) * 4;
    cudaFuncSetAttribute(k_mgemm<64, 2, false, true>,
                         cudaFuncAttributeMaxDynamicSharedMemorySize, SM64);
    cudaFuncSetAttribute(k_mgemm<128, 2, false, false>,
                         cudaFuncAttributeMaxDynamicSharedMemorySize, SM128);
    cudaFuncSetAttribute(k_mgemm<128, 1, true, false>,
                         cudaFuncAttributeMaxDynamicSharedMemorySize, SM128);

    cudaStream_t s1 = g_fork.s1;

    // fork: CSR build on s1; wcat + GEMM0 on main
    cudaEventRecord(g_fork.e0, 0);
    cudaStreamWaitEvent(s1, g_fork.e0, 0);

    cudaMemsetAsync(cur, 0, (size_t)N * sizeof(int), s1);
    k_count  <<<(E + TB - 1) / TB, TB, 0, s1>>>(dst, cur, E);
    k_bsum   <<<nb, 1024, 0, s1>>>(cur, bsum, N);
    k_bscan  <<<1, 64, 0, s1>>>(bsum, nb);
    k_scan2  <<<nb, 1024, 0, s1>>>(cur, bsum, row, cur, N, E);
    k_scatter<<<(E + TB - 1) / TB, TB, 0, s1>>>(src, dst, cur, col, E);
    cudaEventRecord(g_fork.e1, s1);

    k_wcat<<<(128 * 128 + TB - 1) / TB, TB>>>(W2, resW2, Wc);
    k_mgemm<64, 2, false, true><<<gB, 256, SM64>>>(
        nullptr, feats, fv, emb, W0, fh, nullptr, al0, ar0, el, er, N);

    cudaStreamWaitEvent(0, g_fork.e1, 0);

    // Layer 0 aggregation -> hB (fp32)
    k_aggr<128, 2, true><<<aggrB128, TB>>>(row, col, el, er, fh, b0, nullptr, hB, N);

    // Layer 1
    k_mgemm<128, 2, false, false><<<gB, 256, SM128>>>(
        hB, nullptr, nullptr, nullptr, W1, fh, nullptr, al1, ar1, el, er, N);
    k_aggr<128, 2, true><<<aggrB128, TB>>>(row, col, el, er, fh, b1, hB, hA, N);

    // Layer 2: combined [W2|resW2]; fh(half, cols 0-63) + residual hB(f32)
    k_mgemm<128, 1, true, false><<<gB, 256, SM128>>>(
        hA, nullptr, nullptr, nullptr, Wc, fh, hB, al2, ar2, el, er, N);
    k_aggr<64, 1, false><<<aggrB64, TB>>>(row, col, el, er, fh, b2, hB, out, N);
}

// round 10
// speedup vs baseline: 1.1780x; 1.1780x over previous
#include <cuda_runtime.h>
#include <cuda_fp16.h>
#include <cstdint>

// ---------------------------------------------------------------------------
// 3-layer GAT, N=50000 nodes, E=800000 edges.
// R10: CLEAN subwarp aggregation (SW-lane subwarp = 1 fp16 row; SW=16 for
//      O=128, SW=8 for O=64), single edge pass with in-register dual-head
//      denominators. GEMM = mma.sync m16n8k8 tf32 (fused scores/embedding).
//      Forked CSR build with memsetAsync + early join.
// ---------------------------------------------------------------------------

#define NMAX 50000
#define EMAX 800000

__device__ float g_hA[NMAX * 128];
__device__ float g_hB[NMAX * 128];
__device__ float g_fh[NMAX * 128];   // used as __half[NMAX*128]
__device__ float g_el[NMAX * 2];
__device__ float g_er[NMAX * 2];
__device__ float g_Wc[128 * 128];
__device__ int   g_row[NMAX + 1];
__device__ int   g_cur[NMAX];
__device__ int   g_col[EMAX];
__device__ int   g_bsum[64];

__device__ __forceinline__ float lrelu(float v) { return v > 0.f ? v : 0.2f * v; }

__device__ __forceinline__ uint32_t f2tf32(float f) {
    uint32_t r;
    asm("cvt.rna.tf32.f32 %0, %1;" : "=r"(r) : "f"(f));
    return r;
}

__device__ __forceinline__ void mma_tf32(float c[4], const uint32_t a[4],
                                         const uint32_t b[2]) {
    asm volatile(
        "mma.sync.aligned.m16n8k8.row.col.f32.tf32.tf32.f32 "
        "{%0,%1,%2,%3}, {%4,%5,%6,%7}, {%8,%9}, {%0,%1,%2,%3};"
        : "+f"(c[0]), "+f"(c[1]), "+f"(c[2]), "+f"(c[3])
        : "r"(a[0]), "r"(a[1]), "r"(a[2]), "r"(a[3]), "r"(b[0]), "r"(b[1]));
}

namespace {
struct ForkRes {
    cudaStream_t s1;
    cudaEvent_t e0, e1;
    ForkRes() {
        cudaStreamCreateWithFlags(&s1, cudaStreamNonBlocking);
        cudaEventCreateWithFlags(&e0, cudaEventDisableTiming);
        cudaEventCreateWithFlags(&e1, cudaEventDisableTiming);
    }
};
ForkRes g_fork;
}

// ---------------------------------------------------------------------------
// CSR build
// ---------------------------------------------------------------------------
__global__ void k_count(const int* __restrict__ dst, int* __restrict__ cnt, int E) {
    int e = blockIdx.x * blockDim.x + threadIdx.x;
    if (e < E) atomicAdd(&cnt[dst[e]], 1);
}
__global__ void k_bsum(const int* __restrict__ cnt, int* __restrict__ bsum, int N) {
    __shared__ int ws[32];
    int i = blockIdx.x * 1024 + threadIdx.x;
    int lane = threadIdx.x & 31, wid = threadIdx.x >> 5;
    int v = (i < N) ? cnt[i] : 0;
#pragma unroll
    for (int o = 16; o > 0; o >>= 1) v += __shfl_xor_sync(0xffffffffu, v, o);
    if (lane == 0) ws[wid] = v;
    __syncthreads();
    if (wid == 0) {
        int x = ws[lane];
#pragma unroll
        for (int o = 16; o > 0; o >>= 1) x += __shfl_xor_sync(0xffffffffu, x, o);
        if (lane == 0) bsum[blockIdx.x] = x;
    }
}
__global__ void k_bscan(int* __restrict__ bsum, int nb) {
    __shared__ int sh[64];
    int tid = threadIdx.x;
    int v = (tid < nb) ? bsum[tid] : 0;
    sh[tid] = v;
    __syncthreads();
#pragma unroll
    for (int o = 1; o < 64; o <<= 1) {
        int t = (tid >= o) ? sh[tid - o] : 0;
        __syncthreads();
        sh[tid] += t;
        __syncthreads();
    }
    if (tid < nb) bsum[tid] = sh[tid] - v;
}
__global__ void k_scan2(const int* __restrict__ cnt, const int* __restrict__ bsum,
                        int* __restrict__ row, int* __restrict__ cur, int N, int E) {
    __shared__ int ws[32];
    int i = blockIdx.x * 1024 + threadIdx.x;
    int lane = threadIdx.x & 31, wid = threadIdx.x >> 5;
    int v = (i < N) ? cnt[i] : 0;
    int x = v;
#pragma unroll
    for (int o = 1; o < 32; o <<= 1) {
        int t = __shfl_up_sync(0xffffffffu, x, o);
        if (lane >= o) x += t;
    }
    if (lane == 31) ws[wid] = x;
    __syncthreads();
    if (wid == 0) {
        int y = ws[lane];
#pragma unroll
        for (int o = 1; o < 32; o <<= 1) {
            int t = __shfl_up_sync(0xffffffffu, y, o);
            if (lane >= o) y += t;
        }
        ws[lane] = y;
    }
    __syncthreads();
    int excl = bsum[blockIdx.x] + (wid ? ws[wid - 1] : 0) + x - v;
    if (i < N) { row[i] = excl; cur[i] = excl; }
    if (i == 0) row[N] = E;
}
__global__ void k_scatter(const int* __restrict__ src, const int* __restrict__ dst,
                          int* __restrict__ cur, int* __restrict__ col, int E) {
    int e = blockIdx.x * blockDim.x + threadIdx.x;
    if (e >= E) return;
    int slot = atomicAdd(&cur[dst[e]], 1);
    col[slot] = src[e];
}
__global__ void k_wcat(const float* __restrict__ W2, const float* __restrict__ resW2,
                       float* __restrict__ Wc) {
    int i = blockIdx.x * blockDim.x + threadIdx.x;
    if (i >= 128 * 128) return;
    int k = i >> 7, j = i & 127;
    Wc[i] = (j < 64) ? W2[k * 64 + j] : resW2[k * 64 + (j - 64)];
}

// ---------------------------------------------------------------------------
// TF32 mma.sync GEMM + fused scores.
// ---------------------------------------------------------------------------
template <int K, int HS, bool SPLIT, bool EMB>
__global__ void __launch_bounds__(256)
k_mgemm(const float* __restrict__ A, const int* __restrict__ feats,
        const float* __restrict__ fv, const float* __restrict__ emb,
        const float* __restrict__ W,
        void* __restrict__ outh, float* __restrict__ out2,
        const float* __restrict__ al, const float* __restrict__ ar,
        float* __restrict__ el, float* __restrict__ er, int N) {
    extern __shared__ char smraw[];
    float*    stage = (float*)smraw;
    uint32_t* sW    = (uint32_t*)(smraw + 64 * 132 * 4);
    uint32_t* sA    = (uint32_t*)(smraw + 64 * 132 * 4 + K * 132 * 4);
    constexpr int SAS = K + 4;

    const int tid = threadIdx.x;
    const int wid = tid >> 5, lane = tid & 31;
    const int g = lane >> 2, t = lane & 3;
    const int row0 = blockIdx.x * 64;
    const int wRow = (wid >> 2) * 32, wCol = (wid & 3) * 32;

    for (int i = tid; i < K * 32; i += 256) {
        int k = i >> 5, c4 = i & 31;
        float4 v = *(const float4*)&W[k * 128 + c4 * 4];
        uint4 u;
        u.x = f2tf32(v.x); u.y = f2tf32(v.y); u.z = f2tf32(v.z); u.w = f2tf32(v.w);
        *(uint4*)&sW[k * 132 + c4 * 4] = u;
    }
    constexpr int C4 = K / 4;
    for (int i = tid; i < 64 * C4; i += 256) {
        int r = i / C4, c4 = i % C4, rr = row0 + r;
        float4 v = make_float4(0.f, 0.f, 0.f, 0.f);
        if (rr < N) {
            if (EMB) {
                float s = fv[rr];
                v = *(const float4*)&emb[(long long)feats[rr] * 64 + c4 * 4];
                v.x *= s; v.y *= s; v.z *= s; v.w *= s;
            } else {
                v = *(const float4*)&A[(size_t)rr * K + c4 * 4];
            }
        }
        uint4 u;
        u.x = f2tf32(v.x); u.y = f2tf32(v.y); u.z = f2tf32(v.z); u.w = f2tf32(v.w);
        *(uint4*)&sA[r * SAS + c4 * 4] = u;
    }
    __syncthreads();

    float c[2][4][4];
#pragma unroll
    for (int mf = 0; mf < 2; mf++)
#pragma unroll
        for (int nf = 0; nf < 4; nf++)
#pragma unroll
            for (int i = 0; i < 4; i++) c[mf][nf][i] = 0.f;

#pragma unroll
    for (int ks = 0; ks < K / 8; ks++) {
        const int k0 = ks * 8;
        uint32_t a[2][4];
#pragma unroll
        for (int mf = 0; mf < 2; mf++) {
            int rb = wRow + mf * 16;
            a[mf][0] = sA[(rb + g)     * SAS + k0 + t];
            a[mf][1] = sA[(rb + g + 8) * SAS + k0 + t];
            a[mf][2] = sA[(rb + g)     * SAS + k0 + t + 4];
            a[mf][3] = sA[(rb + g + 8) * SAS + k0 + t + 4];
        }
        uint32_t b[4][2];
#pragma unroll
        for (int nf = 0; nf < 4; nf++) {
            int cc = wCol + nf * 8 + g;
            b[nf][0] = sW[(k0 + t)     * 132 + cc];
            b[nf][1] = sW[(k0 + t + 4) * 132 + cc];
        }
#pragma unroll
        for (int mf = 0; mf < 2; mf++)
#pragma unroll
            for (int nf = 0; nf < 4; nf++)
                mma_tf32(c[mf][nf], a[mf], b[nf]);
    }
    __syncthreads();

#pragma unroll
    for (int mf = 0; mf < 2; mf++) {
#pragma unroll
        for (int nf = 0; nf < 4; nf++) {
            int ra = wRow + mf * 16 + g;
            int cc = wCol + nf * 8 + t * 2;
            *(float2*)&stage[ra * 132 + cc]       = make_float2(c[mf][nf][0], c[mf][nf][1]);
            *(float2*)&stage[(ra + 8) * 132 + cc] = make_float2(c[mf][nf][2], c[mf][nf][3]);
        }
    }
    __syncthreads();

    float4 a4 = make_float4(0.f, 0.f, 0.f, 0.f);
    float4 r4 = make_float4(0.f, 0.f, 0.f, 0.f);
    if (lane * 4 < HS * 64) {
        a4 = *(const float4*)&al[lane * 4];
        r4 = *(const float4*)&ar[lane * 4];
    }
    __half* fhh = (__half*)outh;
#pragma unroll
    for (int q = 0; q < 8; q++) {
        int r = wid * 8 + q;
        int rr = row0 + r;
        float4 f = *(const float4*)&stage[r * 132 + lane * 4];
        float sl = f.x * a4.x + f.y * a4.y + f.z * a4.z + f.w * a4.w;
        float sr = f.x * r4.x + f.y * r4.y + f.z * r4.z + f.w * r4.w;
#pragma unroll
        for (int off = 8; off > 0; off >>= 1) {
            sl += __shfl_xor_sync(0xffffffffu, sl, off);
            sr += __shfl_xor_sync(0xffffffffu, sr, off);
        }
        int h = lane >> 4;
        if ((lane & 15) == 0 && h < HS && rr < N) {
            el[rr * HS + h] = sl;
            er[rr * HS + h] = sr;
        }
        if (rr < N) {
            __half2 ha = __float22half2_rn(make_float2(f.x, f.y));
            __half2 hb = __float22half2_rn(make_float2(f.z, f.w));
            uint2 u;
            u.x = *(uint32_t*)&ha; u.y = *(uint32_t*)&hb;
            if (SPLIT) {
                if (lane < 16) *(uint2*)(fhh + (size_t)rr * 64 + lane * 4) = u;
                else           *(float4*)&out2[(size_t)rr * 64 + lane * 4 - 64] = f;
            } else {
                *(uint2*)(fhh + (size_t)rr * 128 + lane * 4) = u;
            }
        }
    }
}

// ---------------------------------------------------------------------------
// Clean subwarp fp16 aggregation. SW = O/8 lanes per subwarp = one fh row
// (uint4 per lane). 32/SW nodes per warp. Single edge pass:
//  - each lane loads one edge's col + computes p0/p1 (both heads)
//  - per-lane dual-head den accumulators (reduced once at the end)
//  - gather: broadcast (s, p0, p1) from each valid lane, 2-deep unroll.
// ---------------------------------------------------------------------------
template <int O, int H, bool ELU>
__global__ void __launch_bounds__(256)
k_aggr(const int* __restrict__ row, const int* __restrict__ col,
       const float* __restrict__ el, const float* __restrict__ er,
       const void* __restrict__ fhv, const float* __restrict__ bias,
       const float* __restrict__ res, float* __restrict__ out, int N) {
    constexpr int SW = O / 8;      // 16 (O=128) or 8 (O=64)
    constexpr int NP = 32 / SW;    // nodes per warp
    const int lane = threadIdx.x & 31;
    const int subw = lane / SW, sub = lane % SW;
    const int warp = (int)((blockIdx.x * blockDim.x + threadIdx.x) >> 5);
    const int w = warp * NP + subw;
    if (w >= N) return;
    const unsigned mask = (((SW == 32) ? 0xffffffffu : ((1u << SW) - 1u)) << (subw * SW));
    const int c0 = sub * 8;
    const bool topHead = (H == 2) && (c0 >= 64);
    const __half* fhh = (const __half*)fhv;

    const float er0 = er[w * H + 0];
    const float er1 = (H == 2) ? er[w * H + 1] : 0.f;
    const int e0 = row[w], e1 = row[w + 1];

    float d0 = 0.f, d1 = 0.f;
    float acc[2][8];
#pragma unroll
    for (int b = 0; b < 2; b++)
#pragma unroll
        for (int i = 0; i < 8; i++) acc[b][i] = 0.f;

    for (int base = e0; base < e1; base += SW) {
        int idx = base + sub;
        bool valid = idx < e1;
        int s_l = valid ? col[idx] : 0;
        float p0_l = 0.f, p1_l = 0.f;
        if (valid) {
            if (H == 2) {
                float2 ev = *(const float2*)&el[s_l * 2];
                p0_l = __expf(lrelu(ev.x + er0));
                p1_l = __expf(lrelu(ev.y + er1));
                d0 += p0_l; d1 += p1_l;
            } else {
                p0_l = __expf(lrelu(el[s_l] + er0));
                d0 += p0_l;
            }
        }
        int n = min(SW, e1 - base);
        int j = 0;
        for (; j + 1 < n; j += 2) {
#pragma unroll
            for (int b = 0; b < 2; b++) {
                int   s  = __shfl_sync(mask, s_l,  j + b, SW);
                float pa = __shfl_sync(mask, p0_l, j + b, SW);
                float p;
                if (H == 2) {
                    float pb = __shfl_sync(mask, p1_l, j + b, SW);
                    p = topHead ? pb : pa;
                } else p = pa;
                uint4 u = *(const uint4*)(fhh + (size_t)s * O + c0);
                float2 f0 = __half22float2(*(__half2*)&u.x);
                float2 f1 = __half22float2(*(__half2*)&u.y);
                float2 f2 = __half22float2(*(__half2*)&u.z);
                float2 f3 = __half22float2(*(__half2*)&u.w);
                acc[b][0] += p * f0.x; acc[b][1] += p * f0.y;
                acc[b][2] += p * f1.x; acc[b][3] += p * f1.y;
                acc[b][4] += p * f2.x; acc[b][5] += p * f2.y;
                acc[b][6] += p * f3.x; acc[b][7] += p * f3.y;
            }
        }
        if (j < n) {
            int   s  = __shfl_sync(mask, s_l,  j, SW);
            float pa = __shfl_sync(mask, p0_l, j, SW);
            float p;
            if (H == 2) {
                float pb = __shfl_sync(mask, p1_l, j, SW);
                p = topHead ? pb : pa;
            } else p = pa;
            uint4 u = *(const uint4*)(fhh + (size_t)s * O + c0);
            float2 f0 = __half22float2(*(__half2*)&u.x);
            float2 f1 = __half22float2(*(__half2*)&u.y);
            float2 f2 = __half22float2(*(__half2*)&u.z);
            float2 f3 = __half22float2(*(__half2*)&u.w);
            acc[0][0] += p * f0.x; acc[0][1] += p * f0.y;
            acc[0][2] += p * f1.x; acc[0][3] += p * f1.y;
            acc[0][4] += p * f2.x; acc[0][5] += p * f2.y;
            acc[0][6] += p * f3.x; acc[0][7] += p * f3.y;
        }
    }

    // reduce dual-head denominators over subwarp
#pragma unroll
    for (int o = SW / 2; o > 0; o >>= 1) {
        d0 += __shfl_xor_sync(mask, d0, o, SW);
        if (H == 2) d1 += __shfl_xor_sync(mask, d1, o, SW);
    }
    float den = (H == 2 && topHead) ? d1 : d0;
    float inv = 1.f / fmaxf(den, 1e-9f);

    float4 bva = *(const float4*)&bias[c0];
    float4 bvb = *(const float4*)&bias[c0 + 4];
    float4 ra = make_float4(0.f, 0.f, 0.f, 0.f), rb = ra;
    if (res) {
        ra = *(const float4*)&res[(size_t)w * O + c0];
        rb = *(const float4*)&res[(size_t)w * O + c0 + 4];
    }
    float o8[8];
    o8[0] = (acc[0][0] + acc[1][0]) * inv + bva.x + ra.x;
    o8[1] = (acc[0][1] + acc[1][1]) * inv + bva.y + ra.y;
    o8[2] = (acc[0][2] + acc[1][2]) * inv + bva.z + ra.z;
    o8[3] = (acc[0][3] + acc[1][3]) * inv + bva.w + ra.w;
    o8[4] = (acc[0][4] + acc[1][4]) * inv + bvb.x + rb.x;
    o8[5] = (acc[0][5] + acc[1][5]) * inv + bvb.y + rb.y;
    o8[6] = (acc[0][6] + acc[1][6]) * inv + bvb.z + rb.z;
    o8[7] = (acc[0][7] + acc[1][7]) * inv + bvb.w + rb.w;
    if (ELU) {
#pragma unroll
        for (int i = 0; i < 8; i++)
            o8[i] = o8[i] > 0.f ? o8[i] : (__expf(o8[i]) - 1.f);
    }
    *(float4*)&out[(size_t)w * O + c0]     = make_float4(o8[0], o8[1], o8[2], o8[3]);
    *(float4*)&out[(size_t)w * O + c0 + 4] = make_float4(o8[4], o8[5], o8[6], o8[7]);
}

// ---------------------------------------------------------------------------
extern "C" void kernel_launch(void* const* d_in, const int* in_sizes, int n_in,
                              void* d_out, int out_size) {
    const int*   feats = (const int*)  d_in[0];
    const float* fv    = (const float*)d_in[1];
    const int*   src   = (const int*)  d_in[2];
    const int*   dst   = (const int*)  d_in[3];
    const float* emb   = (const float*)d_in[4];
    const float* W0    = (const float*)d_in[5];
    const float* al0   = (const float*)d_in[6];
    const float* ar0   = (const float*)d_in[7];
    const float* b0    = (const float*)d_in[8];
    const float* W1    = (const float*)d_in[9];
    const float* al1   = (const float*)d_in[10];
    const float* ar1   = (const float*)d_in[11];
    const float* b1    = (const float*)d_in[12];
    const float* W2    = (const float*)d_in[13];
    const float* al2   = (const float*)d_in[14];
    const float* ar2   = (const float*)d_in[15];
    const float* b2    = (const float*)d_in[16];
    const float* resW2 = (const float*)d_in[17];
    float* out = (float*)d_out;

    const int N = in_sizes[0] / 8;
    const int E = in_sizes[2];

    float *hA, *hB, *fh, *el, *er, *Wc;
    int *row, *cur, *col, *bsum;
    cudaGetSymbolAddress((void**)&hA,   g_hA);
    cudaGetSymbolAddress((void**)&hB,   g_hB);
    cudaGetSymbolAddress((void**)&fh,   g_fh);
    cudaGetSymbolAddress((void**)&el,   g_el);
    cudaGetSymbolAddress((void**)&er,   g_er);
    cudaGetSymbolAddress((void**)&Wc,   g_Wc);
    cudaGetSymbolAddress((void**)&row,  g_row);
    cudaGetSymbolAddress((void**)&cur,  g_cur);
    cudaGetSymbolAddress((void**)&col,  g_col);
    cudaGetSymbolAddress((void**)&bsum, g_bsum);

    const int TB = 256;
    const int gB = (N + 63) / 64;
    const int nb = (N + 1023) / 1024;
    const int aggrB128 = ((N + 1) / 2 + 7) / 8;   // NP=2, 8 warps/block
    const int aggrB64  = ((N + 3) / 4 + 7) / 8;   // NP=4

    const int SM64  = 64 * 132 * 4 + 64 * 132 * 4  + 64 * (64 + 4)  * 4;
    const int SM128 = 64 * 132 * 4 + 128 * 132 * 4 + 64 * (128 + 4) * 4;
    cudaFuncSetAttribute(k_mgemm<64, 2, false, true>,
                         cudaFuncAttributeMaxDynamicSharedMemorySize, SM64);
    cudaFuncSetAttribute(k_mgemm<128, 2, false, false>,
                         cudaFuncAttributeMaxDynamicSharedMemorySize, SM128);
    cudaFuncSetAttribute(k_mgemm<128, 1, true, false>,
                         cudaFuncAttributeMaxDynamicSharedMemorySize, SM128);

    cudaStream_t s1 = g_fork.s1;

    // fork: CSR build on s1; wcat + GEMM0 on main
    cudaEventRecord(g_fork.e0, 0);
    cudaStreamWaitEvent(s1, g_fork.e0, 0);

    cudaMemsetAsync(cur, 0, (size_t)N * sizeof(int), s1);
    k_count  <<<(E + TB - 1) / TB, TB, 0, s1>>>(dst, cur, E);
    k_bsum   <<<nb, 1024, 0, s1>>>(cur, bsum, N);
    k_bscan  <<<1, 64, 0, s1>>>(bsum, nb);
    k_scan2  <<<nb, 1024, 0, s1>>>(cur, bsum, row, cur, N, E);
    k_scatter<<<(E + TB - 1) / TB, TB, 0, s1>>>(src, dst, cur, col, E);
    cudaEventRecord(g_fork.e1, s1);

    k_wcat<<<(128 * 128 + TB - 1) / TB, TB>>>(W2, resW2, Wc);
    k_mgemm<64, 2, false, true><<<gB, 256, SM64>>>(
        nullptr, feats, fv, emb, W0, fh, nullptr, al0, ar0, el, er, N);

    cudaStreamWaitEvent(0, g_fork.e1, 0);

    // Layer 0 aggregation -> hB (fp32)
    k_aggr<128, 2, true><<<aggrB128, TB>>>(row, col, el, er, fh, b0, nullptr, hB, N);

    // Layer 1
    k_mgemm<128, 2, false, false><<<gB, 256, SM128>>>(
        hB, nullptr, nullptr, nullptr, W1, fh, nullptr, al1, ar1, el, er, N);
    k_aggr<128, 2, true><<<aggrB128, TB>>>(row, col, el, er, fh, b1, hB, hA, N);

    // Layer 2: combined [W2|resW2]; fh(half, cols 0-63) + residual hB(f32)
    k_mgemm<128, 1, true, false><<<gB, 256, SM128>>>(
        hA, nullptr, nullptr, nullptr, Wc, fh, hB, al2, ar2, el, er, N);
    k_aggr<64, 1, false><<<aggrB64, TB>>>(row, col, el, er, fh, b2, hB, out, N);
}